// round 1
// baseline (speedup 1.0000x reference)
#include <cuda_runtime.h>
#include <cuda_bf16.h>
#include <math.h>

// ---------------- problem constants ----------------
#define B_SZ 2
#define T_SEQ 2048
#define D_MODEL 2048
#define N_HEADS 16
#define HEAD_DIM 128
#define D_FF 5504
#define M_ROWS (B_SZ * T_SEQ)          // 4096
#define ATTN_SCALE 0.08838834764831845f // 1/sqrt(128)

// ---------------- scratch (device globals; no runtime allocation) ----------------
__device__ float g_h [(size_t)M_ROWS * D_MODEL];
__device__ float g_q [(size_t)M_ROWS * D_MODEL];
__device__ float g_k [(size_t)M_ROWS * D_MODEL];
__device__ float g_v [(size_t)M_ROWS * D_MODEL];
__device__ float g_a [(size_t)M_ROWS * D_MODEL];
__device__ float g_x2[(size_t)M_ROWS * D_MODEL];
__device__ float g_h2[(size_t)M_ROWS * D_MODEL];
__device__ float g_f1[(size_t)M_ROWS * D_FF];
__device__ float g_f2[(size_t)M_ROWS * D_FF];

// ---------------- RMSNorm: one block per row ----------------
__global__ void __launch_bounds__(256) rmsnorm_k(const float* __restrict__ x,
                                                 const float* __restrict__ w,
                                                 float* __restrict__ out, int Dm) {
    int row = blockIdx.x;
    const float* xr = x + (size_t)row * Dm;
    float ss = 0.f;
    for (int i = threadIdx.x; i < Dm; i += 256) { float v = xr[i]; ss += v * v; }
    __shared__ float red[256];
    red[threadIdx.x] = ss;
    __syncthreads();
    for (int s = 128; s > 0; s >>= 1) {
        if (threadIdx.x < s) red[threadIdx.x] += red[threadIdx.x + s];
        __syncthreads();
    }
    float rms = sqrtf(red[0] / (float)Dm);
    float inv = 1.0f / (rms + 1e-8f);
    float* orow = out + (size_t)row * Dm;
    for (int i = threadIdx.x; i < Dm; i += 256) orow[i] = w[i] * xr[i] * inv;
}

// ---------------- SGEMM: C[M,N] = A[M,K] * B[N,K]^T (+ optional add) ----------------
// BM=BN=128, BK=8, 256 threads, 8x8 per-thread microtile.
// Requires M%128==0, N%128==0, K%8==0 (true for all call sites here).
__global__ void __launch_bounds__(256) gemm_abt(const float* __restrict__ A,
                                                const float* __restrict__ Bm,
                                                const float* __restrict__ addsrc,
                                                float* __restrict__ C,
                                                int Mi, int Ni, int Ki) {
    __shared__ float As[8][128];
    __shared__ float Bs[8][128];
    const int bm = blockIdx.y * 128;
    const int bn = blockIdx.x * 128;
    const int tid = threadIdx.x;
    const int tx = tid & 15;   // 0..15 -> N groups of 8
    const int ty = tid >> 4;   // 0..15 -> M groups of 8

    float acc[8][8];
#pragma unroll
    for (int i = 0; i < 8; i++)
#pragma unroll
        for (int j = 0; j < 8; j++) acc[i][j] = 0.f;

    const int lr = tid >> 1;          // 0..127
    const int lk = (tid & 1) * 4;     // 0 or 4
    const float* Aptr = A + (size_t)(bm + lr) * Ki + lk;
    const float* Bptr = Bm + (size_t)(bn + lr) * Ki + lk;

    for (int k0 = 0; k0 < Ki; k0 += 8) {
        float4 a4 = *(const float4*)(Aptr + k0);
        float4 b4 = *(const float4*)(Bptr + k0);
        As[lk + 0][lr] = a4.x; As[lk + 1][lr] = a4.y; As[lk + 2][lr] = a4.z; As[lk + 3][lr] = a4.w;
        Bs[lk + 0][lr] = b4.x; Bs[lk + 1][lr] = b4.y; Bs[lk + 2][lr] = b4.z; Bs[lk + 3][lr] = b4.w;
        __syncthreads();
#pragma unroll
        for (int k = 0; k < 8; k++) {
            float ar[8], br[8];
            *(float4*)&ar[0] = *(const float4*)&As[k][ty * 8];
            *(float4*)&ar[4] = *(const float4*)&As[k][ty * 8 + 4];
            *(float4*)&br[0] = *(const float4*)&Bs[k][tx * 8];
            *(float4*)&br[4] = *(const float4*)&Bs[k][tx * 8 + 4];
#pragma unroll
            for (int i = 0; i < 8; i++)
#pragma unroll
                for (int j = 0; j < 8; j++) acc[i][j] += ar[i] * br[j];
        }
        __syncthreads();
    }

#pragma unroll
    for (int i = 0; i < 8; i++) {
        int r = bm + ty * 8 + i;
#pragma unroll
        for (int j = 0; j < 8; j += 4) {
            size_t idx = (size_t)r * Ni + bn + tx * 8 + j;
            float4 o;
            o.x = acc[i][j + 0]; o.y = acc[i][j + 1]; o.z = acc[i][j + 2]; o.w = acc[i][j + 3];
            if (addsrc) {
                float4 s = *(const float4*)(addsrc + idx);
                o.x += s.x; o.y += s.y; o.z += s.z; o.w += s.w;
            }
            *(float4*)(C + idx) = o;
        }
    }
}

// ---------------- RoPE (in-place on Q and K) ----------------
__global__ void __launch_bounds__(256) rope_k(float* __restrict__ q, float* __restrict__ k,
                                              const float* __restrict__ cs,
                                              const float* __restrict__ sn) {
    int idx = blockIdx.x * 256 + threadIdx.x;      // M_ROWS * N_HEADS * 64 threads
    int d = idx & 63;
    int head = (idx >> 6) & (N_HEADS - 1);
    int row = idx >> 10;
    if (row >= M_ROWS) return;
    int t = row & (T_SEQ - 1);
    float c1 = cs[t * HEAD_DIM + d],      s1 = sn[t * HEAD_DIM + d];
    float c2 = cs[t * HEAD_DIM + d + 64], s2 = sn[t * HEAD_DIM + d + 64];
    size_t base = (size_t)row * D_MODEL + head * HEAD_DIM;
    float q1 = q[base + d], q2 = q[base + d + 64];
    q[base + d]      = q1 * c1 - q2 * s1;
    q[base + d + 64] = q2 * c2 + q1 * s2;
    float k1 = k[base + d], k2 = k[base + d + 64];
    k[base + d]      = k1 * c1 - k2 * s1;
    k[base + d + 64] = k2 * c2 + k1 * s2;
}

// ---------------- Flash attention (causal, fp32, online softmax) ----------------
// grid: (T/64, N_HEADS, B), 256 threads. Dynamic smem.
#define QS_STRIDE 129
#define KS_STRIDE 129
#define VS_STRIDE 132
#define PS_STRIDE 65
// floats: Qs 64*129 + Ks 64*129 + Vs 64*132 + Ps 64*65 + red 64*16 + m/l/alpha 3*64
#define ATTN_SMEM_FLOATS (64*QS_STRIDE + 64*KS_STRIDE + 64*VS_STRIDE + 64*PS_STRIDE + 64*16 + 192)
#define ATTN_SMEM_BYTES  (ATTN_SMEM_FLOATS * 4)

__global__ void __launch_bounds__(256) flash_attn_k(const float* __restrict__ Q,
                                                    const float* __restrict__ K,
                                                    const float* __restrict__ V,
                                                    float* __restrict__ O) {
    extern __shared__ float sm[];
    float* Qs  = sm;
    float* Ks  = Qs + 64 * QS_STRIDE;
    float* Vs  = Ks + 64 * KS_STRIDE;
    float* Ps  = Vs + 64 * VS_STRIDE;
    float* red = Ps + 64 * PS_STRIDE;
    float* m_s = red + 64 * 16;
    float* l_s = m_s + 64;
    float* a_s = l_s + 64;

    const int qt = blockIdx.x, h = blockIdx.y, b = blockIdx.z;
    const int tid = threadIdx.x, tx = tid & 15, ty = tid >> 4;
    const size_t qrow0 = (size_t)(b * T_SEQ + qt * 64);
    const size_t col0 = (size_t)h * HEAD_DIM;

    // load Q tile
#pragma unroll
    for (int it = 0; it < 8; it++) {
        int flat = tid + it * 256;
        int r = flat >> 5, c4 = (flat & 31) * 4;
        float4 v4 = *(const float4*)(Q + (qrow0 + r) * D_MODEL + col0 + c4);
        float* dst = Qs + r * QS_STRIDE + c4;
        dst[0] = v4.x; dst[1] = v4.y; dst[2] = v4.z; dst[3] = v4.w;
    }
    if (tid < 64) { m_s[tid] = -1e30f; l_s[tid] = 0.f; }
    float acc[4][8];
#pragma unroll
    for (int i = 0; i < 4; i++)
#pragma unroll
        for (int j = 0; j < 8; j++) acc[i][j] = 0.f;
    __syncthreads();

    for (int kt = 0; kt <= qt; kt++) {
        size_t krow0 = (size_t)(b * T_SEQ + kt * 64);
#pragma unroll
        for (int it = 0; it < 8; it++) {
            int flat = tid + it * 256;
            int r = flat >> 5, c4 = (flat & 31) * 4;
            float4 kv = *(const float4*)(K + (krow0 + r) * D_MODEL + col0 + c4);
            float* kd = Ks + r * KS_STRIDE + c4;
            kd[0] = kv.x; kd[1] = kv.y; kd[2] = kv.z; kd[3] = kv.w;
            float4 vv = *(const float4*)(V + (krow0 + r) * D_MODEL + col0 + c4);
            *(float4*)(Vs + r * VS_STRIDE + c4) = vv;
        }
        __syncthreads();

        // S = Q K^T (scaled), thread tile 4x4
        float s[4][4];
#pragma unroll
        for (int i = 0; i < 4; i++)
#pragma unroll
            for (int j = 0; j < 4; j++) s[i][j] = 0.f;
        for (int d = 0; d < HEAD_DIM; d++) {
            float qf[4], kf[4];
#pragma unroll
            for (int i = 0; i < 4; i++) qf[i] = Qs[(ty * 4 + i) * QS_STRIDE + d];
#pragma unroll
            for (int j = 0; j < 4; j++) kf[j] = Ks[(tx * 4 + j) * KS_STRIDE + d];
#pragma unroll
            for (int i = 0; i < 4; i++)
#pragma unroll
                for (int j = 0; j < 4; j++) s[i][j] += qf[i] * kf[j];
        }
        bool diag = (kt == qt);
#pragma unroll
        for (int i = 0; i < 4; i++)
#pragma unroll
            for (int j = 0; j < 4; j++) {
                s[i][j] *= ATTN_SCALE;
                if (diag && (tx * 4 + j) > (ty * 4 + i)) s[i][j] += -1e9f;
            }

        // row max
#pragma unroll
        for (int i = 0; i < 4; i++) {
            float rm = fmaxf(fmaxf(s[i][0], s[i][1]), fmaxf(s[i][2], s[i][3]));
            red[(ty * 4 + i) * 16 + tx] = rm;
        }
        __syncthreads();
        if (tid < 64) {
            float mx = m_s[tid];
#pragma unroll
            for (int t2 = 0; t2 < 16; t2++) mx = fmaxf(mx, red[tid * 16 + t2]);
            a_s[tid] = expf(m_s[tid] - mx);
            m_s[tid] = mx;
        }
        __syncthreads();

        // P = exp(S - m), row sums
        float rs[4] = {0.f, 0.f, 0.f, 0.f};
#pragma unroll
        for (int i = 0; i < 4; i++) {
            float mrow = m_s[ty * 4 + i];
#pragma unroll
            for (int j = 0; j < 4; j++) {
                float p = expf(s[i][j] - mrow);
                Ps[(ty * 4 + i) * PS_STRIDE + tx * 4 + j] = p;
                rs[i] += p;
            }
        }
#pragma unroll
        for (int i = 0; i < 4; i++) red[(ty * 4 + i) * 16 + tx] = rs[i];
        __syncthreads();
        if (tid < 64) {
            float sum = 0.f;
#pragma unroll
            for (int t2 = 0; t2 < 16; t2++) sum += red[tid * 16 + t2];
            l_s[tid] = l_s[tid] * a_s[tid] + sum;
        }

        // O = O*alpha + P @ V   (thread tile: 4 rows x 8 cols)
#pragma unroll
        for (int i = 0; i < 4; i++) {
            float a = a_s[ty * 4 + i];
#pragma unroll
            for (int jj = 0; jj < 8; jj++) acc[i][jj] *= a;
        }
        for (int k = 0; k < 64; k++) {
            float vf[8];
#pragma unroll
            for (int jj = 0; jj < 8; jj++) vf[jj] = Vs[k * VS_STRIDE + tx * 8 + jj];
#pragma unroll
            for (int i = 0; i < 4; i++) {
                float p = Ps[(ty * 4 + i) * PS_STRIDE + k];
#pragma unroll
                for (int jj = 0; jj < 8; jj++) acc[i][jj] += p * vf[jj];
            }
        }
        __syncthreads();
    }

    // epilogue: divide by l, write out
#pragma unroll
    for (int i = 0; i < 4; i++) {
        int r = ty * 4 + i;
        float inv = 1.0f / l_s[r];
        size_t orow = (qrow0 + r) * D_MODEL + col0 + tx * 8;
#pragma unroll
        for (int jj = 0; jj < 8; jj++) O[orow + jj] = acc[i][jj] * inv;
    }
}

// ---------------- SiLU gate: f1 = silu(f1) * f2 ----------------
__global__ void __launch_bounds__(256) silu_gate_k(float* __restrict__ f1,
                                                   const float* __restrict__ f2, int n) {
    int i = blockIdx.x * 256 + threadIdx.x;
    if (i < n) {
        float z = f1[i];
        float sil = z / (1.0f + expf(-z));
        f1[i] = sil * f2[i];
    }
}

// ---------------- launch ----------------
extern "C" void kernel_launch(void* const* d_in, const int* in_sizes, int n_in,
                              void* d_out, int out_size) {
    const float* x    = (const float*)d_in[0];
    const float* cs   = (const float*)d_in[1];
    const float* sn   = (const float*)d_in[2];
    // d_in[3] = mask (unused; causality applied analytically)
    const float* g1   = (const float*)d_in[4];
    const float* g2   = (const float*)d_in[5];
    const float* Wq   = (const float*)d_in[6];
    const float* Wk   = (const float*)d_in[7];
    const float* Wv   = (const float*)d_in[8];
    const float* Wo   = (const float*)d_in[9];
    const float* W1   = (const float*)d_in[10];
    const float* W2   = (const float*)d_in[11];
    const float* Wout = (const float*)d_in[12];
    float* out = (float*)d_out;

    float *ph, *pq, *pk, *pv, *pa, *px2, *ph2, *pf1, *pf2;
    cudaGetSymbolAddress((void**)&ph,  g_h);
    cudaGetSymbolAddress((void**)&pq,  g_q);
    cudaGetSymbolAddress((void**)&pk,  g_k);
    cudaGetSymbolAddress((void**)&pv,  g_v);
    cudaGetSymbolAddress((void**)&pa,  g_a);
    cudaGetSymbolAddress((void**)&px2, g_x2);
    cudaGetSymbolAddress((void**)&ph2, g_h2);
    cudaGetSymbolAddress((void**)&pf1, g_f1);
    cudaGetSymbolAddress((void**)&pf2, g_f2);

    cudaFuncSetAttribute(flash_attn_k, cudaFuncAttributeMaxDynamicSharedMemorySize,
                         ATTN_SMEM_BYTES);

    // 1) h = rmsnorm(x, g1)
    rmsnorm_k<<<M_ROWS, 256>>>(x, g1, ph, D_MODEL);

    // 2) Q/K/V projections
    dim3 gproj(D_MODEL / 128, M_ROWS / 128);
    gemm_abt<<<gproj, 256>>>(ph, Wq, nullptr, pq, M_ROWS, D_MODEL, D_MODEL);
    gemm_abt<<<gproj, 256>>>(ph, Wk, nullptr, pk, M_ROWS, D_MODEL, D_MODEL);
    gemm_abt<<<gproj, 256>>>(ph, Wv, nullptr, pv, M_ROWS, D_MODEL, D_MODEL);

    // 3) RoPE on Q,K
    rope_k<<<(M_ROWS * N_HEADS * 64) / 256, 256>>>(pq, pk, cs, sn);

    // 4) causal flash attention -> g_a
    dim3 gattn(T_SEQ / 64, N_HEADS, B_SZ);
    flash_attn_k<<<gattn, 256, ATTN_SMEM_BYTES>>>(pq, pk, pv, pa);

    // 5) x2 = x + attn @ Wo^T
    gemm_abt<<<gproj, 256>>>(pa, Wo, x, px2, M_ROWS, D_MODEL, D_MODEL);

    // 6) h2 = rmsnorm(x2, g2)
    rmsnorm_k<<<M_ROWS, 256>>>(px2, g2, ph2, D_MODEL);

    // 7) FF gates
    dim3 gff(D_FF / 128, M_ROWS / 128);
    gemm_abt<<<gff, 256>>>(ph2, W1, nullptr, pf1, M_ROWS, D_FF, D_MODEL);
    gemm_abt<<<gff, 256>>>(ph2, W2, nullptr, pf2, M_ROWS, D_FF, D_MODEL);

    // 8) f1 = silu(f1) * f2
    int nff = M_ROWS * D_FF;
    silu_gate_k<<<(nff + 255) / 256, 256>>>(pf1, pf2, nff);

    // 9) out = x2 + f1 @ Wout^T
    gemm_abt<<<gproj, 256>>>(pf1, Wout, px2, out, M_ROWS, D_MODEL, D_FF);
}

// round 2
// speedup vs baseline: 2.3961x; 2.3961x over previous
#include <cuda_runtime.h>
#include <cuda_bf16.h>
#include <math.h>
#include <stdint.h>

// ---------------- problem constants ----------------
#define B_SZ 2
#define T_SEQ 2048
#define D_MODEL 2048
#define N_HEADS 16
#define HEAD_DIM 128
#define D_FF 5504
#define M_ROWS (B_SZ * T_SEQ)          // 4096
#define ATTN_SCALE 0.08838834764831845f // 1/sqrt(128)

// ---------------- scratch (device globals; no runtime allocation) ----------------
__device__ float g_h [(size_t)M_ROWS * D_MODEL];
__device__ float g_q [(size_t)M_ROWS * D_MODEL];
__device__ float g_k [(size_t)M_ROWS * D_MODEL];
__device__ float g_v [(size_t)M_ROWS * D_MODEL];
__device__ float g_a [(size_t)M_ROWS * D_MODEL];
__device__ float g_x2[(size_t)M_ROWS * D_MODEL];
__device__ float g_h2[(size_t)M_ROWS * D_MODEL];
__device__ float g_f1[(size_t)M_ROWS * D_FF];
__device__ float g_f2[(size_t)M_ROWS * D_FF];

// ---------------- RMSNorm: one block per row ----------------
__global__ void __launch_bounds__(256) rmsnorm_k(const float* __restrict__ x,
                                                 const float* __restrict__ w,
                                                 float* __restrict__ out, int Dm) {
    int row = blockIdx.x;
    const float* xr = x + (size_t)row * Dm;
    float ss = 0.f;
    for (int i = threadIdx.x; i < Dm; i += 256) { float v = xr[i]; ss += v * v; }
    __shared__ float red[256];
    red[threadIdx.x] = ss;
    __syncthreads();
    for (int s = 128; s > 0; s >>= 1) {
        if (threadIdx.x < s) red[threadIdx.x] += red[threadIdx.x + s];
        __syncthreads();
    }
    float rms = sqrtf(red[0] / (float)Dm);
    float inv = 1.0f / (rms + 1e-8f);
    float* orow = out + (size_t)row * Dm;
    for (int i = threadIdx.x; i < Dm; i += 256) orow[i] = w[i] * xr[i] * inv;
}

// ---------------- TF32 tensor-core GEMM: C[M,N] = A[M,K] * B[N,K]^T (+add) ----
// BM=BN=128, BK=16, 256 threads = 8 warps (4 m x 2 n), warp tile 32x64.
// mma.sync.m16n8k8.tf32, fp32 accumulate. Requires M%128==0,N%128==0,K%16==0.
#define BM 128
#define BN 128
#define BK 16
#define SSTRIDE 20   // BK + 4 pad -> conflict-free fragment loads

__device__ __forceinline__ uint32_t f2tf32(float f) {
    uint32_t r;
    asm("cvt.rna.tf32.f32 %0, %1;" : "=r"(r) : "f"(f));
    return r;
}

__device__ __forceinline__ void mma_tf32(float (&d)[4], const uint32_t (&a)[4],
                                         uint32_t b0, uint32_t b1) {
    asm volatile("mma.sync.aligned.m16n8k8.row.col.f32.tf32.tf32.f32 "
                 "{%0,%1,%2,%3}, {%4,%5,%6,%7}, {%8,%9}, {%0,%1,%2,%3};"
                 : "+f"(d[0]), "+f"(d[1]), "+f"(d[2]), "+f"(d[3])
                 : "r"(a[0]), "r"(a[1]), "r"(a[2]), "r"(a[3]), "r"(b0), "r"(b1));
}

__global__ void __launch_bounds__(256) gemm_tf32(const float* __restrict__ A,
                                                 const float* __restrict__ Bm,
                                                 const float* __restrict__ addsrc,
                                                 float* __restrict__ C,
                                                 int Mi, int Ni, int Ki) {
    __shared__ uint32_t As[2][BM * SSTRIDE];
    __shared__ uint32_t Bs[2][BN * SSTRIDE];

    const int tid = threadIdx.x;
    const int wid = tid >> 5;
    const int lane = tid & 31;
    const int g = lane >> 2;      // 0..7
    const int t = lane & 3;       // 0..3
    const int wm = wid & 3;       // 0..3 (m)
    const int wn = wid >> 2;      // 0..1 (n)
    const int bm = blockIdx.y * BM;
    const int bn = blockIdx.x * BN;

    float acc[2][8][4];
#pragma unroll
    for (int i = 0; i < 2; i++)
#pragma unroll
        for (int j = 0; j < 8; j++)
#pragma unroll
            for (int l = 0; l < 4; l++) acc[i][j][l] = 0.f;

    // gmem load mapping: flat = tid + it*256, row = flat>>2, k4 = (flat&3)*4
    const int r0 = tid >> 2;          // 0..63
    const int c4 = (tid & 3) * 4;     // 0,4,8,12
    const float* Ap0 = A  + (size_t)(bm + r0)      * Ki + c4;
    const float* Ap1 = A  + (size_t)(bm + r0 + 64) * Ki + c4;
    const float* Bp0 = Bm + (size_t)(bn + r0)      * Ki + c4;
    const float* Bp1 = Bm + (size_t)(bn + r0 + 64) * Ki + c4;

    const int nk = Ki / BK;

    // preload tile 0
    float4 a0 = *(const float4*)(Ap0);
    float4 a1 = *(const float4*)(Ap1);
    float4 b0 = *(const float4*)(Bp0);
    float4 b1 = *(const float4*)(Bp1);
    {
        uint32_t* d0 = &As[0][r0 * SSTRIDE + c4];
        d0[0] = f2tf32(a0.x); d0[1] = f2tf32(a0.y); d0[2] = f2tf32(a0.z); d0[3] = f2tf32(a0.w);
        uint32_t* d1 = &As[0][(r0 + 64) * SSTRIDE + c4];
        d1[0] = f2tf32(a1.x); d1[1] = f2tf32(a1.y); d1[2] = f2tf32(a1.z); d1[3] = f2tf32(a1.w);
        uint32_t* e0 = &Bs[0][r0 * SSTRIDE + c4];
        e0[0] = f2tf32(b0.x); e0[1] = f2tf32(b0.y); e0[2] = f2tf32(b0.z); e0[3] = f2tf32(b0.w);
        uint32_t* e1 = &Bs[0][(r0 + 64) * SSTRIDE + c4];
        e1[0] = f2tf32(b1.x); e1[1] = f2tf32(b1.y); e1[2] = f2tf32(b1.z); e1[3] = f2tf32(b1.w);
    }
    __syncthreads();

    for (int kt = 0; kt < nk; kt++) {
        const int cur = kt & 1;
        const bool more = (kt + 1) < nk;
        if (more) {
            int ko = (kt + 1) * BK;
            a0 = *(const float4*)(Ap0 + ko);
            a1 = *(const float4*)(Ap1 + ko);
            b0 = *(const float4*)(Bp0 + ko);
            b1 = *(const float4*)(Bp1 + ko);
        }

        // compute on buffer cur
#pragma unroll
        for (int ks = 0; ks < 2; ks++) {
            const int kb = ks * 8;
            uint32_t af[2][4];
#pragma unroll
            for (int mt = 0; mt < 2; mt++) {
                int rr = wm * 32 + mt * 16 + g;
                af[mt][0] = As[cur][rr * SSTRIDE + kb + t];
                af[mt][1] = As[cur][(rr + 8) * SSTRIDE + kb + t];
                af[mt][2] = As[cur][rr * SSTRIDE + kb + t + 4];
                af[mt][3] = As[cur][(rr + 8) * SSTRIDE + kb + t + 4];
            }
#pragma unroll
            for (int nt = 0; nt < 8; nt++) {
                int cc = wn * 64 + nt * 8 + g;
                uint32_t bf0 = Bs[cur][cc * SSTRIDE + kb + t];
                uint32_t bf1 = Bs[cur][cc * SSTRIDE + kb + t + 4];
                mma_tf32(acc[0][nt], af[0], bf0, bf1);
                mma_tf32(acc[1][nt], af[1], bf0, bf1);
            }
        }

        if (more) {
            const int nxt = cur ^ 1;
            uint32_t* d0 = &As[nxt][r0 * SSTRIDE + c4];
            d0[0] = f2tf32(a0.x); d0[1] = f2tf32(a0.y); d0[2] = f2tf32(a0.z); d0[3] = f2tf32(a0.w);
            uint32_t* d1 = &As[nxt][(r0 + 64) * SSTRIDE + c4];
            d1[0] = f2tf32(a1.x); d1[1] = f2tf32(a1.y); d1[2] = f2tf32(a1.z); d1[3] = f2tf32(a1.w);
            uint32_t* e0 = &Bs[nxt][r0 * SSTRIDE + c4];
            e0[0] = f2tf32(b0.x); e0[1] = f2tf32(b0.y); e0[2] = f2tf32(b0.z); e0[3] = f2tf32(b0.w);
            uint32_t* e1 = &Bs[nxt][(r0 + 64) * SSTRIDE + c4];
            e1[0] = f2tf32(b1.x); e1[1] = f2tf32(b1.y); e1[2] = f2tf32(b1.z); e1[3] = f2tf32(b1.w);
            __syncthreads();
        }
    }

    // epilogue
#pragma unroll
    for (int mt = 0; mt < 2; mt++) {
#pragma unroll
        for (int nt = 0; nt < 8; nt++) {
            int r = bm + wm * 32 + mt * 16 + g;
            int c = bn + wn * 64 + nt * 8 + t * 2;
            size_t i0 = (size_t)r * Ni + c;
            size_t i1 = i0 + (size_t)8 * Ni;
            float2 o0 = make_float2(acc[mt][nt][0], acc[mt][nt][1]);
            float2 o1 = make_float2(acc[mt][nt][2], acc[mt][nt][3]);
            if (addsrc) {
                float2 s0 = *(const float2*)(addsrc + i0);
                float2 s1 = *(const float2*)(addsrc + i1);
                o0.x += s0.x; o0.y += s0.y;
                o1.x += s1.x; o1.y += s1.y;
            }
            *(float2*)(C + i0) = o0;
            *(float2*)(C + i1) = o1;
        }
    }
}

// ---------------- RoPE (in-place on Q and K) ----------------
__global__ void __launch_bounds__(256) rope_k(float* __restrict__ q, float* __restrict__ k,
                                              const float* __restrict__ cs,
                                              const float* __restrict__ sn) {
    int idx = blockIdx.x * 256 + threadIdx.x;
    int d = idx & 63;
    int head = (idx >> 6) & (N_HEADS - 1);
    int row = idx >> 10;
    if (row >= M_ROWS) return;
    int t = row & (T_SEQ - 1);
    float c1 = cs[t * HEAD_DIM + d],      s1 = sn[t * HEAD_DIM + d];
    float c2 = cs[t * HEAD_DIM + d + 64], s2 = sn[t * HEAD_DIM + d + 64];
    size_t base = (size_t)row * D_MODEL + head * HEAD_DIM;
    float q1 = q[base + d], q2 = q[base + d + 64];
    q[base + d]      = q1 * c1 - q2 * s1;
    q[base + d + 64] = q2 * c2 + q1 * s2;
    float k1 = k[base + d], k2 = k[base + d + 64];
    k[base + d]      = k1 * c1 - k2 * s1;
    k[base + d + 64] = k2 * c2 + k1 * s2;
}

// ---------------- Flash attention (causal, fp32, online softmax) ----------------
#define QS_STRIDE 129
#define KS_STRIDE 129
#define VS_STRIDE 132
#define PS_STRIDE 65
#define ATTN_SMEM_FLOATS (64*QS_STRIDE + 64*KS_STRIDE + 64*VS_STRIDE + 64*PS_STRIDE + 64*16 + 192)
#define ATTN_SMEM_BYTES  (ATTN_SMEM_FLOATS * 4)

__global__ void __launch_bounds__(256) flash_attn_k(const float* __restrict__ Q,
                                                    const float* __restrict__ K,
                                                    const float* __restrict__ V,
                                                    float* __restrict__ O) {
    extern __shared__ float sm[];
    float* Qs  = sm;
    float* Ks  = Qs + 64 * QS_STRIDE;
    float* Vs  = Ks + 64 * KS_STRIDE;
    float* Ps  = Vs + 64 * VS_STRIDE;
    float* red = Ps + 64 * PS_STRIDE;
    float* m_s = red + 64 * 16;
    float* l_s = m_s + 64;
    float* a_s = l_s + 64;

    const int qt = blockIdx.x, h = blockIdx.y, b = blockIdx.z;
    const int tid = threadIdx.x, tx = tid & 15, ty = tid >> 4;
    const size_t qrow0 = (size_t)(b * T_SEQ + qt * 64);
    const size_t col0 = (size_t)h * HEAD_DIM;

#pragma unroll
    for (int it = 0; it < 8; it++) {
        int flat = tid + it * 256;
        int r = flat >> 5, c4 = (flat & 31) * 4;
        float4 v4 = *(const float4*)(Q + (qrow0 + r) * D_MODEL + col0 + c4);
        float* dst = Qs + r * QS_STRIDE + c4;
        dst[0] = v4.x; dst[1] = v4.y; dst[2] = v4.z; dst[3] = v4.w;
    }
    if (tid < 64) { m_s[tid] = -1e30f; l_s[tid] = 0.f; }
    float acc[4][8];
#pragma unroll
    for (int i = 0; i < 4; i++)
#pragma unroll
        for (int j = 0; j < 8; j++) acc[i][j] = 0.f;
    __syncthreads();

    for (int kt = 0; kt <= qt; kt++) {
        size_t krow0 = (size_t)(b * T_SEQ + kt * 64);
#pragma unroll
        for (int it = 0; it < 8; it++) {
            int flat = tid + it * 256;
            int r = flat >> 5, c4 = (flat & 31) * 4;
            float4 kv = *(const float4*)(K + (krow0 + r) * D_MODEL + col0 + c4);
            float* kd = Ks + r * KS_STRIDE + c4;
            kd[0] = kv.x; kd[1] = kv.y; kd[2] = kv.z; kd[3] = kv.w;
            float4 vv = *(const float4*)(V + (krow0 + r) * D_MODEL + col0 + c4);
            *(float4*)(Vs + r * VS_STRIDE + c4) = vv;
        }
        __syncthreads();

        float s[4][4];
#pragma unroll
        for (int i = 0; i < 4; i++)
#pragma unroll
            for (int j = 0; j < 4; j++) s[i][j] = 0.f;
        for (int d = 0; d < HEAD_DIM; d++) {
            float qf[4], kf[4];
#pragma unroll
            for (int i = 0; i < 4; i++) qf[i] = Qs[(ty * 4 + i) * QS_STRIDE + d];
#pragma unroll
            for (int j = 0; j < 4; j++) kf[j] = Ks[(tx * 4 + j) * KS_STRIDE + d];
#pragma unroll
            for (int i = 0; i < 4; i++)
#pragma unroll
                for (int j = 0; j < 4; j++) s[i][j] += qf[i] * kf[j];
        }
        bool diag = (kt == qt);
#pragma unroll
        for (int i = 0; i < 4; i++)
#pragma unroll
            for (int j = 0; j < 4; j++) {
                s[i][j] *= ATTN_SCALE;
                if (diag && (tx * 4 + j) > (ty * 4 + i)) s[i][j] += -1e9f;
            }

#pragma unroll
        for (int i = 0; i < 4; i++) {
            float rm = fmaxf(fmaxf(s[i][0], s[i][1]), fmaxf(s[i][2], s[i][3]));
            red[(ty * 4 + i) * 16 + tx] = rm;
        }
        __syncthreads();
        if (tid < 64) {
            float mx = m_s[tid];
#pragma unroll
            for (int t2 = 0; t2 < 16; t2++) mx = fmaxf(mx, red[tid * 16 + t2]);
            a_s[tid] = expf(m_s[tid] - mx);
            m_s[tid] = mx;
        }
        __syncthreads();

        float rs[4] = {0.f, 0.f, 0.f, 0.f};
#pragma unroll
        for (int i = 0; i < 4; i++) {
            float mrow = m_s[ty * 4 + i];
#pragma unroll
            for (int j = 0; j < 4; j++) {
                float p = expf(s[i][j] - mrow);
                Ps[(ty * 4 + i) * PS_STRIDE + tx * 4 + j] = p;
                rs[i] += p;
            }
        }
#pragma unroll
        for (int i = 0; i < 4; i++) red[(ty * 4 + i) * 16 + tx] = rs[i];
        __syncthreads();
        if (tid < 64) {
            float sum = 0.f;
#pragma unroll
            for (int t2 = 0; t2 < 16; t2++) sum += red[tid * 16 + t2];
            l_s[tid] = l_s[tid] * a_s[tid] + sum;
        }

#pragma unroll
        for (int i = 0; i < 4; i++) {
            float a = a_s[ty * 4 + i];
#pragma unroll
            for (int jj = 0; jj < 8; jj++) acc[i][jj] *= a;
        }
        for (int k = 0; k < 64; k++) {
            float vf[8];
#pragma unroll
            for (int jj = 0; jj < 8; jj++) vf[jj] = Vs[k * VS_STRIDE + tx * 8 + jj];
#pragma unroll
            for (int i = 0; i < 4; i++) {
                float p = Ps[(ty * 4 + i) * PS_STRIDE + k];
#pragma unroll
                for (int jj = 0; jj < 8; jj++) acc[i][jj] += p * vf[jj];
            }
        }
        __syncthreads();
    }

#pragma unroll
    for (int i = 0; i < 4; i++) {
        int r = ty * 4 + i;
        float inv = 1.0f / l_s[r];
        size_t orow = (qrow0 + r) * D_MODEL + col0 + tx * 8;
#pragma unroll
        for (int jj = 0; jj < 8; jj++) O[orow + jj] = acc[i][jj] * inv;
    }
}

// ---------------- SiLU gate: f1 = silu(f1) * f2 ----------------
__global__ void __launch_bounds__(256) silu_gate_k(float* __restrict__ f1,
                                                   const float* __restrict__ f2, int n) {
    int i = blockIdx.x * 256 + threadIdx.x;
    if (i < n) {
        float z = f1[i];
        float sil = z / (1.0f + expf(-z));
        f1[i] = sil * f2[i];
    }
}

// ---------------- launch ----------------
extern "C" void kernel_launch(void* const* d_in, const int* in_sizes, int n_in,
                              void* d_out, int out_size) {
    const float* x    = (const float*)d_in[0];
    const float* cs   = (const float*)d_in[1];
    const float* sn   = (const float*)d_in[2];
    const float* g1   = (const float*)d_in[4];
    const float* g2   = (const float*)d_in[5];
    const float* Wq   = (const float*)d_in[6];
    const float* Wk   = (const float*)d_in[7];
    const float* Wv   = (const float*)d_in[8];
    const float* Wo   = (const float*)d_in[9];
    const float* W1   = (const float*)d_in[10];
    const float* W2   = (const float*)d_in[11];
    const float* Wout = (const float*)d_in[12];
    float* out = (float*)d_out;

    float *ph, *pq, *pk, *pv, *pa, *px2, *ph2, *pf1, *pf2;
    cudaGetSymbolAddress((void**)&ph,  g_h);
    cudaGetSymbolAddress((void**)&pq,  g_q);
    cudaGetSymbolAddress((void**)&pk,  g_k);
    cudaGetSymbolAddress((void**)&pv,  g_v);
    cudaGetSymbolAddress((void**)&pa,  g_a);
    cudaGetSymbolAddress((void**)&px2, g_x2);
    cudaGetSymbolAddress((void**)&ph2, g_h2);
    cudaGetSymbolAddress((void**)&pf1, g_f1);
    cudaGetSymbolAddress((void**)&pf2, g_f2);

    cudaFuncSetAttribute(flash_attn_k, cudaFuncAttributeMaxDynamicSharedMemorySize,
                         ATTN_SMEM_BYTES);

    // 1) h = rmsnorm(x, g1)
    rmsnorm_k<<<M_ROWS, 256>>>(x, g1, ph, D_MODEL);

    // 2) Q/K/V projections (tf32 tensor cores)
    dim3 gproj(D_MODEL / 128, M_ROWS / 128);
    gemm_tf32<<<gproj, 256>>>(ph, Wq, nullptr, pq, M_ROWS, D_MODEL, D_MODEL);
    gemm_tf32<<<gproj, 256>>>(ph, Wk, nullptr, pk, M_ROWS, D_MODEL, D_MODEL);
    gemm_tf32<<<gproj, 256>>>(ph, Wv, nullptr, pv, M_ROWS, D_MODEL, D_MODEL);

    // 3) RoPE on Q,K
    rope_k<<<(M_ROWS * N_HEADS * 64) / 256, 256>>>(pq, pk, cs, sn);

    // 4) causal flash attention -> g_a
    dim3 gattn(T_SEQ / 64, N_HEADS, B_SZ);
    flash_attn_k<<<gattn, 256, ATTN_SMEM_BYTES>>>(pq, pk, pv, pa);

    // 5) x2 = x + attn @ Wo^T
    gemm_tf32<<<gproj, 256>>>(pa, Wo, x, px2, M_ROWS, D_MODEL, D_MODEL);

    // 6) h2 = rmsnorm(x2, g2)
    rmsnorm_k<<<M_ROWS, 256>>>(px2, g2, ph2, D_MODEL);

    // 7) FF gates
    dim3 gff(D_FF / 128, M_ROWS / 128);
    gemm_tf32<<<gff, 256>>>(ph2, W1, nullptr, pf1, M_ROWS, D_FF, D_MODEL);
    gemm_tf32<<<gff, 256>>>(ph2, W2, nullptr, pf2, M_ROWS, D_FF, D_MODEL);

    // 8) f1 = silu(f1) * f2
    int nff = M_ROWS * D_FF;
    silu_gate_k<<<(nff + 255) / 256, 256>>>(pf1, pf2, nff);

    // 9) out = x2 + f1 @ Wout^T
    gemm_tf32<<<gproj, 256>>>(pf1, Wout, px2, out, M_ROWS, D_MODEL, D_FF);
}

// round 4
// speedup vs baseline: 3.8393x; 1.6023x over previous
#include <cuda_runtime.h>
#include <cuda_fp16.h>
#include <math.h>
#include <stdint.h>

// ---------------- problem constants ----------------
#define B_SZ 2
#define T_SEQ 2048
#define D_MODEL 2048
#define N_HEADS 16
#define HEAD_DIM 128
#define D_FF 5504
#define M_ROWS (B_SZ * T_SEQ)          // 4096
#define ATTN_SCALE 0.08838834764831845f // 1/sqrt(128)

// ---------------- scratch (device globals; no runtime allocation) ----------------
__device__ __align__(1024) __half g_h [(size_t)M_ROWS * D_MODEL];
__device__ __align__(1024) float  g_q [(size_t)M_ROWS * D_MODEL];
__device__ __align__(1024) float  g_k [(size_t)M_ROWS * D_MODEL];
__device__ __align__(1024) float  g_v [(size_t)M_ROWS * D_MODEL];
__device__ __align__(1024) __half g_a [(size_t)M_ROWS * D_MODEL];
__device__ __align__(1024) float  g_x2[(size_t)M_ROWS * D_MODEL];
__device__ __align__(1024) __half g_h2[(size_t)M_ROWS * D_MODEL];
__device__ __align__(1024) float  g_f1[(size_t)M_ROWS * D_FF];
__device__ __align__(1024) float  g_f2[(size_t)M_ROWS * D_FF];
__device__ __align__(1024) __half g_f1h[(size_t)M_ROWS * D_FF];
// half weights: Wq,Wk,Wv,Wo (D*D each), W1,W2,Wout (DFF*D each)
#define O_WQ   ((size_t)0)
#define O_WK   ((size_t)D_MODEL * D_MODEL)
#define O_WV   ((size_t)2 * D_MODEL * D_MODEL)
#define O_WO   ((size_t)3 * D_MODEL * D_MODEL)
#define O_W1   ((size_t)4 * D_MODEL * D_MODEL)
#define O_W2   (O_W1 + (size_t)D_FF * D_MODEL)
#define O_WOUT (O_W2 + (size_t)D_FF * D_MODEL)
#define WBUF_TOTAL (O_WOUT + (size_t)D_FF * D_MODEL)
__device__ __align__(1024) __half g_wbuf[WBUF_TOTAL];

// ---------------- helpers ----------------
__device__ __forceinline__ uint32_t smem_u32(const void* p) {
    uint32_t a;
    asm("{ .reg .u64 t; cvta.to.shared.u64 t, %1; cvt.u32.u64 %0, t; }" : "=r"(a) : "l"(p));
    return a;
}
__device__ __forceinline__ void cp_async16(uint32_t dst, const void* src) {
    asm volatile("cp.async.cg.shared.global [%0], [%1], 16;" :: "r"(dst), "l"(src));
}
#define CP_COMMIT() asm volatile("cp.async.commit_group;" ::: "memory")
#define CP_WAIT(N)  asm volatile("cp.async.wait_group %0;" :: "n"(N) : "memory")

__device__ __forceinline__ void mma_f16(float (&d)[4], uint32_t a0, uint32_t a1,
                                        uint32_t a2, uint32_t a3, uint32_t b0, uint32_t b1) {
    asm volatile("mma.sync.aligned.m16n8k16.row.col.f32.f16.f16.f32 "
                 "{%0,%1,%2,%3}, {%4,%5,%6,%7}, {%8,%9}, {%0,%1,%2,%3};"
                 : "+f"(d[0]), "+f"(d[1]), "+f"(d[2]), "+f"(d[3])
                 : "r"(a0), "r"(a1), "r"(a2), "r"(a3), "r"(b0), "r"(b1));
}

// ---------------- fp16 tensor-core GEMM: C[M,N] = A[M,K] * B[N,K]^T (+add) -----
// 128x128 tile, BK=32, 3-stage cp.async ring, 256 threads = 8 warps (4m x 2n),
// warp tile 32x64, mma m16n8k16 fp16 -> fp32.
// smem row stride: 40 halves = 20 u32 (conflict-free fragment loads).
#define GS_STRIDE_U32 20
#define GS_STRIDE_B   80
#define STAGE_A_B   10240          // 128 rows * 80 B
#define STAGE_PAIR  20480
#define GSTAGES 3
#define GEMM_SMEM_BYTES (GSTAGES * STAGE_PAIR)   // 61440

__global__ void __launch_bounds__(256) gemm_f16(const __half* __restrict__ A,
                                                const __half* __restrict__ Bw,
                                                const float* __restrict__ addsrc,
                                                float* __restrict__ C,
                                                int Ni, int Ki) {
    extern __shared__ char smem[];
    const uint32_t sbase = smem_u32(smem);
    const int tid = threadIdx.x;
    const int wid = tid >> 5, lane = tid & 31;
    const int g = lane >> 2, t = lane & 3;
    const int wm = wid & 3, wn = wid >> 2;
    const int bm = blockIdx.y * 128, bn = blockIdx.x * 128;

    float acc[2][8][4];
#pragma unroll
    for (int i = 0; i < 2; i++)
#pragma unroll
        for (int j = 0; j < 8; j++)
#pragma unroll
            for (int l = 0; l < 4; l++) acc[i][j][l] = 0.f;

    // loader mapping: chunk c in [0,512): row=c>>2, seg=c&3 (16B of 8 halves)
    const int row0 = tid >> 2;        // 0..63
    const int seg0 = tid & 3;         // 0..3
    const __half* aSrc = A  + (size_t)(bm + row0) * Ki + seg0 * 8;
    const __half* bSrc = Bw + (size_t)(bn + row0) * Ki + seg0 * 8;
    const size_t rowJump = (size_t)64 * Ki;
    const uint32_t dOff = (uint32_t)(row0 * GS_STRIDE_B + seg0 * 16);

    const int nk = Ki / 32;

#define LOAD_STAGE(s) do { \
        uint32_t _base = sbase + (uint32_t)((s) % GSTAGES) * STAGE_PAIR + dOff; \
        const __half* _ap = aSrc + (size_t)(s) * 32; \
        const __half* _bp = bSrc + (size_t)(s) * 32; \
        cp_async16(_base, _ap); \
        cp_async16(_base + 64 * GS_STRIDE_B, _ap + rowJump); \
        cp_async16(_base + STAGE_A_B, _bp); \
        cp_async16(_base + STAGE_A_B + 64 * GS_STRIDE_B, _bp + rowJump); \
        CP_COMMIT(); \
    } while (0)

    LOAD_STAGE(0);
    LOAD_STAGE(1);

    for (int kt = 0; kt < nk; kt++) {
        if (kt + 2 < nk) LOAD_STAGE(kt + 2);
        if (kt + 2 < nk)      { CP_WAIT(2); }
        else if (kt + 1 < nk) { CP_WAIT(1); }
        else                  { CP_WAIT(0); }
        __syncthreads();

        const uint32_t* As32 = (const uint32_t*)(smem + (kt % GSTAGES) * STAGE_PAIR);
        const uint32_t* Bs32 = (const uint32_t*)(smem + (kt % GSTAGES) * STAGE_PAIR + STAGE_A_B);

#pragma unroll
        for (int ks = 0; ks < 2; ks++) {
            const int kb = ks * 8;
            uint32_t af[2][4];
#pragma unroll
            for (int mt = 0; mt < 2; mt++) {
                int rb = wm * 32 + mt * 16 + g;
                af[mt][0] = As32[rb * GS_STRIDE_U32 + kb + t];
                af[mt][1] = As32[(rb + 8) * GS_STRIDE_U32 + kb + t];
                af[mt][2] = As32[rb * GS_STRIDE_U32 + kb + t + 4];
                af[mt][3] = As32[(rb + 8) * GS_STRIDE_U32 + kb + t + 4];
            }
#pragma unroll
            for (int nt = 0; nt < 8; nt++) {
                int cb = wn * 64 + nt * 8 + g;
                uint32_t b0 = Bs32[cb * GS_STRIDE_U32 + kb + t];
                uint32_t b1 = Bs32[cb * GS_STRIDE_U32 + kb + t + 4];
                mma_f16(acc[0][nt], af[0][0], af[0][1], af[0][2], af[0][3], b0, b1);
                mma_f16(acc[1][nt], af[1][0], af[1][1], af[1][2], af[1][3], b0, b1);
            }
        }
        __syncthreads();
    }
#undef LOAD_STAGE

    // epilogue
#pragma unroll
    for (int mt = 0; mt < 2; mt++) {
#pragma unroll
        for (int nt = 0; nt < 8; nt++) {
            int r = bm + wm * 32 + mt * 16 + g;
            int c = bn + wn * 64 + nt * 8 + t * 2;
            size_t i0 = (size_t)r * Ni + c;
            size_t i1 = i0 + (size_t)8 * Ni;
            float2 o0 = make_float2(acc[mt][nt][0], acc[mt][nt][1]);
            float2 o1 = make_float2(acc[mt][nt][2], acc[mt][nt][3]);
            if (addsrc) {
                float2 s0 = *(const float2*)(addsrc + i0);
                float2 s1 = *(const float2*)(addsrc + i1);
                o0.x += s0.x; o0.y += s0.y;
                o1.x += s1.x; o1.y += s1.y;
            }
            *(float2*)(C + i0) = o0;
            *(float2*)(C + i1) = o1;
        }
    }
}

// ---------------- fp32 -> fp16 conversion ----------------
__global__ void __launch_bounds__(256) tohalf_k(const float4* __restrict__ in,
                                                __half2* __restrict__ out, int n4) {
    int i = blockIdx.x * 256 + threadIdx.x;
    if (i < n4) {
        float4 v = in[i];
        out[i * 2]     = __floats2half2_rn(v.x, v.y);
        out[i * 2 + 1] = __floats2half2_rn(v.z, v.w);
    }
}

// ---------------- RMSNorm: one block per row, fp16 out ----------------
__global__ void __launch_bounds__(256) rmsnorm_k(const float* __restrict__ x,
                                                 const float* __restrict__ w,
                                                 __half* __restrict__ out, int Dm) {
    int row = blockIdx.x;
    const float* xr = x + (size_t)row * Dm;
    float ss = 0.f;
    for (int i = threadIdx.x; i < Dm; i += 256) { float v = xr[i]; ss += v * v; }
    __shared__ float red[256];
    red[threadIdx.x] = ss;
    __syncthreads();
    for (int s = 128; s > 0; s >>= 1) {
        if (threadIdx.x < s) red[threadIdx.x] += red[threadIdx.x + s];
        __syncthreads();
    }
    float rms = sqrtf(red[0] / (float)Dm);
    float inv = 1.0f / (rms + 1e-8f);
    __half* orow = out + (size_t)row * Dm;
    for (int i = threadIdx.x; i < Dm; i += 256) orow[i] = __float2half_rn(w[i] * xr[i] * inv);
}

// ---------------- RoPE (in-place on fp32 Q and K) ----------------
__global__ void __launch_bounds__(256) rope_k(float* __restrict__ q, float* __restrict__ k,
                                              const float* __restrict__ cs,
                                              const float* __restrict__ sn) {
    int idx = blockIdx.x * 256 + threadIdx.x;
    int d = idx & 63;
    int head = (idx >> 6) & (N_HEADS - 1);
    int row = idx >> 10;
    if (row >= M_ROWS) return;
    int t = row & (T_SEQ - 1);
    float c1 = cs[t * HEAD_DIM + d],      s1 = sn[t * HEAD_DIM + d];
    float c2 = cs[t * HEAD_DIM + d + 64], s2 = sn[t * HEAD_DIM + d + 64];
    size_t base = (size_t)row * D_MODEL + head * HEAD_DIM;
    float q1 = q[base + d], q2 = q[base + d + 64];
    q[base + d]      = q1 * c1 - q2 * s1;
    q[base + d + 64] = q2 * c2 + q1 * s2;
    float k1 = k[base + d], k2 = k[base + d + 64];
    k[base + d]      = k1 * c1 - k2 * s1;
    k[base + d + 64] = k2 * c2 + k1 * s2;
}

// ---------------- Flash attention (causal, fp32 compute, fp16 out) ----------------
#define QS_STRIDE 129
#define KS_STRIDE 129
#define VS_STRIDE 132
#define PS_STRIDE 65
#define ATTN_SMEM_FLOATS (64*QS_STRIDE + 64*KS_STRIDE + 64*VS_STRIDE + 64*PS_STRIDE + 64*16 + 192)
#define ATTN_SMEM_BYTES  (ATTN_SMEM_FLOATS * 4)

__global__ void __launch_bounds__(256) flash_attn_k(const float* __restrict__ Q,
                                                    const float* __restrict__ K,
                                                    const float* __restrict__ V,
                                                    __half* __restrict__ O) {
    extern __shared__ float sm[];
    float* Qs  = sm;
    float* Ks  = Qs + 64 * QS_STRIDE;
    float* Vs  = Ks + 64 * KS_STRIDE;
    float* Ps  = Vs + 64 * VS_STRIDE;
    float* red = Ps + 64 * PS_STRIDE;
    float* m_s = red + 64 * 16;
    float* l_s = m_s + 64;
    float* a_s = l_s + 64;

    const int qt = blockIdx.x, h = blockIdx.y, b = blockIdx.z;
    const int tid = threadIdx.x, tx = tid & 15, ty = tid >> 4;
    const size_t qrow0 = (size_t)(b * T_SEQ + qt * 64);
    const size_t col0 = (size_t)h * HEAD_DIM;

#pragma unroll
    for (int it = 0; it < 8; it++) {
        int flat = tid + it * 256;
        int r = flat >> 5, c4 = (flat & 31) * 4;
        float4 v4 = *(const float4*)(Q + (qrow0 + r) * D_MODEL + col0 + c4);
        float* dst = Qs + r * QS_STRIDE + c4;
        dst[0] = v4.x; dst[1] = v4.y; dst[2] = v4.z; dst[3] = v4.w;
    }
    if (tid < 64) { m_s[tid] = -1e30f; l_s[tid] = 0.f; }
    float acc[4][8];
#pragma unroll
    for (int i = 0; i < 4; i++)
#pragma unroll
        for (int j = 0; j < 8; j++) acc[i][j] = 0.f;
    __syncthreads();

    for (int kt = 0; kt <= qt; kt++) {
        size_t krow0 = (size_t)(b * T_SEQ + kt * 64);
#pragma unroll
        for (int it = 0; it < 8; it++) {
            int flat = tid + it * 256;
            int r = flat >> 5, c4 = (flat & 31) * 4;
            float4 kv = *(const float4*)(K + (krow0 + r) * D_MODEL + col0 + c4);
            float* kd = Ks + r * KS_STRIDE + c4;
            kd[0] = kv.x; kd[1] = kv.y; kd[2] = kv.z; kd[3] = kv.w;
            float4 vv = *(const float4*)(V + (krow0 + r) * D_MODEL + col0 + c4);
            *(float4*)(Vs + r * VS_STRIDE + c4) = vv;
        }
        __syncthreads();

        float s[4][4];
#pragma unroll
        for (int i = 0; i < 4; i++)
#pragma unroll
            for (int j = 0; j < 4; j++) s[i][j] = 0.f;
        for (int d = 0; d < HEAD_DIM; d++) {
            float qf[4], kf[4];
#pragma unroll
            for (int i = 0; i < 4; i++) qf[i] = Qs[(ty * 4 + i) * QS_STRIDE + d];
#pragma unroll
            for (int j = 0; j < 4; j++) kf[j] = Ks[(tx * 4 + j) * KS_STRIDE + d];
#pragma unroll
            for (int i = 0; i < 4; i++)
#pragma unroll
                for (int j = 0; j < 4; j++) s[i][j] += qf[i] * kf[j];
        }
        bool diag = (kt == qt);
#pragma unroll
        for (int i = 0; i < 4; i++)
#pragma unroll
            for (int j = 0; j < 4; j++) {
                s[i][j] *= ATTN_SCALE;
                if (diag && (tx * 4 + j) > (ty * 4 + i)) s[i][j] += -1e9f;
            }

#pragma unroll
        for (int i = 0; i < 4; i++) {
            float rm = fmaxf(fmaxf(s[i][0], s[i][1]), fmaxf(s[i][2], s[i][3]));
            red[(ty * 4 + i) * 16 + tx] = rm;
        }
        __syncthreads();
        if (tid < 64) {
            float mx = m_s[tid];
#pragma unroll
            for (int t2 = 0; t2 < 16; t2++) mx = fmaxf(mx, red[tid * 16 + t2]);
            a_s[tid] = expf(m_s[tid] - mx);
            m_s[tid] = mx;
        }
        __syncthreads();

        float rs[4] = {0.f, 0.f, 0.f, 0.f};
#pragma unroll
        for (int i = 0; i < 4; i++) {
            float mrow = m_s[ty * 4 + i];
#pragma unroll
            for (int j = 0; j < 4; j++) {
                float p = expf(s[i][j] - mrow);
                Ps[(ty * 4 + i) * PS_STRIDE + tx * 4 + j] = p;
                rs[i] += p;
            }
        }
#pragma unroll
        for (int i = 0; i < 4; i++) red[(ty * 4 + i) * 16 + tx] = rs[i];
        __syncthreads();
        if (tid < 64) {
            float sum = 0.f;
#pragma unroll
            for (int t2 = 0; t2 < 16; t2++) sum += red[tid * 16 + t2];
            l_s[tid] = l_s[tid] * a_s[tid] + sum;
        }

#pragma unroll
        for (int i = 0; i < 4; i++) {
            float a = a_s[ty * 4 + i];
#pragma unroll
            for (int jj = 0; jj < 8; jj++) acc[i][jj] *= a;
        }
        for (int k = 0; k < 64; k++) {
            float vf[8];
#pragma unroll
            for (int jj = 0; jj < 8; jj++) vf[jj] = Vs[k * VS_STRIDE + tx * 8 + jj];
#pragma unroll
            for (int i = 0; i < 4; i++) {
                float p = Ps[(ty * 4 + i) * PS_STRIDE + k];
#pragma unroll
                for (int jj = 0; jj < 8; jj++) acc[i][jj] += p * vf[jj];
            }
        }
        __syncthreads();
    }

#pragma unroll
    for (int i = 0; i < 4; i++) {
        int r = ty * 4 + i;
        float inv = 1.0f / l_s[r];
        size_t orow = (qrow0 + r) * D_MODEL + col0 + tx * 8;
#pragma unroll
        for (int jj = 0; jj < 8; jj++) O[orow + jj] = __float2half_rn(acc[i][jj] * inv);
    }
}

// ---------------- SiLU gate: f1h = half(silu(f1) * f2) ----------------
__global__ void __launch_bounds__(256) silu_gate_k(const float* __restrict__ f1,
                                                   const float* __restrict__ f2,
                                                   __half* __restrict__ oh, int n) {
    int i = blockIdx.x * 256 + threadIdx.x;
    if (i < n) {
        float z = f1[i];
        float sil = z / (1.0f + expf(-z));
        oh[i] = __float2half_rn(sil * f2[i]);
    }
}

// ---------------- launch ----------------
extern "C" void kernel_launch(void* const* d_in, const int* in_sizes, int n_in,
                              void* d_out, int out_size) {
    const float* x    = (const float*)d_in[0];
    const float* cs   = (const float*)d_in[1];
    const float* sn   = (const float*)d_in[2];
    const float* g1   = (const float*)d_in[4];
    const float* g2   = (const float*)d_in[5];
    const float* Wq   = (const float*)d_in[6];
    const float* Wk   = (const float*)d_in[7];
    const float* Wv   = (const float*)d_in[8];
    const float* Wo   = (const float*)d_in[9];
    const float* W1   = (const float*)d_in[10];
    const float* W2   = (const float*)d_in[11];
    const float* Wout = (const float*)d_in[12];
    float* out = (float*)d_out;

    __half *ph, *pa, *ph2, *pf1h, *pw;
    float *pq, *pk, *pv, *px2, *pf1, *pf2;
    cudaGetSymbolAddress((void**)&ph,   g_h);
    cudaGetSymbolAddress((void**)&pq,   g_q);
    cudaGetSymbolAddress((void**)&pk,   g_k);
    cudaGetSymbolAddress((void**)&pv,   g_v);
    cudaGetSymbolAddress((void**)&pa,   g_a);
    cudaGetSymbolAddress((void**)&px2,  g_x2);
    cudaGetSymbolAddress((void**)&ph2,  g_h2);
    cudaGetSymbolAddress((void**)&pf1,  g_f1);
    cudaGetSymbolAddress((void**)&pf2,  g_f2);
    cudaGetSymbolAddress((void**)&pf1h, g_f1h);
    cudaGetSymbolAddress((void**)&pw,   g_wbuf);

    cudaFuncSetAttribute(flash_attn_k, cudaFuncAttributeMaxDynamicSharedMemorySize,
                         ATTN_SMEM_BYTES);
    cudaFuncSetAttribute(gemm_f16, cudaFuncAttributeMaxDynamicSharedMemorySize,
                         GEMM_SMEM_BYTES);

    // 0) convert weights to fp16
    const int nDD = D_MODEL * D_MODEL;
    const int nFD = D_FF * D_MODEL;
    tohalf_k<<<nDD / 1024, 256>>>((const float4*)Wq,   (__half2*)(pw + O_WQ),   nDD / 4);
    tohalf_k<<<nDD / 1024, 256>>>((const float4*)Wk,   (__half2*)(pw + O_WK),   nDD / 4);
    tohalf_k<<<nDD / 1024, 256>>>((const float4*)Wv,   (__half2*)(pw + O_WV),   nDD / 4);
    tohalf_k<<<nDD / 1024, 256>>>((const float4*)Wo,   (__half2*)(pw + O_WO),   nDD / 4);
    tohalf_k<<<nFD / 1024, 256>>>((const float4*)W1,   (__half2*)(pw + O_W1),   nFD / 4);
    tohalf_k<<<nFD / 1024, 256>>>((const float4*)W2,   (__half2*)(pw + O_W2),   nFD / 4);
    tohalf_k<<<nFD / 1024, 256>>>((const float4*)Wout, (__half2*)(pw + O_WOUT), nFD / 4);

    // 1) h = rmsnorm(x, g1)  (fp16 out)
    rmsnorm_k<<<M_ROWS, 256>>>(x, g1, ph, D_MODEL);

    // 2) Q/K/V projections (fp16 HMMA)
    dim3 gproj(D_MODEL / 128, M_ROWS / 128);
    gemm_f16<<<gproj, 256, GEMM_SMEM_BYTES>>>(ph, pw + O_WQ, nullptr, pq, D_MODEL, D_MODEL);
    gemm_f16<<<gproj, 256, GEMM_SMEM_BYTES>>>(ph, pw + O_WK, nullptr, pk, D_MODEL, D_MODEL);
    gemm_f16<<<gproj, 256, GEMM_SMEM_BYTES>>>(ph, pw + O_WV, nullptr, pv, D_MODEL, D_MODEL);

    // 3) RoPE on Q,K (fp32)
    rope_k<<<(M_ROWS * N_HEADS * 64) / 256, 256>>>(pq, pk, cs, sn);

    // 4) causal flash attention -> fp16
    dim3 gattn(T_SEQ / 64, N_HEADS, B_SZ);
    flash_attn_k<<<gattn, 256, ATTN_SMEM_BYTES>>>(pq, pk, pv, pa);

    // 5) x2 = x + attn @ Wo^T
    gemm_f16<<<gproj, 256, GEMM_SMEM_BYTES>>>(pa, pw + O_WO, x, px2, D_MODEL, D_MODEL);

    // 6) h2 = rmsnorm(x2, g2)
    rmsnorm_k<<<M_ROWS, 256>>>(px2, g2, ph2, D_MODEL);

    // 7) FF gates
    dim3 gff(D_FF / 128, M_ROWS / 128);
    gemm_f16<<<gff, 256, GEMM_SMEM_BYTES>>>(ph2, pw + O_W1, nullptr, pf1, D_FF, D_MODEL);
    gemm_f16<<<gff, 256, GEMM_SMEM_BYTES>>>(ph2, pw + O_W2, nullptr, pf2, D_FF, D_MODEL);

    // 8) f1h = half(silu(f1) * f2)
    int nff = M_ROWS * D_FF;
    silu_gate_k<<<(nff + 255) / 256, 256>>>(pf1, pf2, pf1h, nff);

    // 9) out = x2 + f1h @ Wout^T
    gemm_f16<<<gproj, 256, GEMM_SMEM_BYTES>>>(pf1h, pw + O_WOUT, px2, out, D_MODEL, D_FF);
}

// round 5
// speedup vs baseline: 6.1762x; 1.6087x over previous
#include <cuda_runtime.h>
#include <cuda_fp16.h>
#include <math.h>
#include <stdint.h>

// ---------------- problem constants ----------------
#define B_SZ 2
#define T_SEQ 2048
#define D_MODEL 2048
#define N_HEADS 16
#define HEAD_DIM 128
#define D_FF 5504
#define M_ROWS (B_SZ * T_SEQ)          // 4096
#define ATTN_SCALE 0.08838834764831845f // 1/sqrt(128)

// ---------------- scratch (device globals; no runtime allocation) ----------------
__device__ __align__(1024) __half g_h  [(size_t)M_ROWS * D_MODEL];
__device__ __align__(1024) __half g_qh [(size_t)M_ROWS * D_MODEL];
__device__ __align__(1024) __half g_kh [(size_t)M_ROWS * D_MODEL];
__device__ __align__(1024) __half g_vh [(size_t)M_ROWS * D_MODEL];
__device__ __align__(1024) __half g_a  [(size_t)M_ROWS * D_MODEL];
__device__ __align__(1024) float  g_x2 [(size_t)M_ROWS * D_MODEL];
__device__ __align__(1024) __half g_h2 [(size_t)M_ROWS * D_MODEL];
__device__ __align__(1024) float  g_f1 [(size_t)M_ROWS * D_FF];
__device__ __align__(1024) float  g_f2 [(size_t)M_ROWS * D_FF];
__device__ __align__(1024) __half g_f1h[(size_t)M_ROWS * D_FF];
// half weights
#define O_WQ   ((size_t)0)
#define O_WK   ((size_t)D_MODEL * D_MODEL)
#define O_WV   ((size_t)2 * D_MODEL * D_MODEL)
#define O_WO   ((size_t)3 * D_MODEL * D_MODEL)
#define O_W1   ((size_t)4 * D_MODEL * D_MODEL)
#define O_W2   (O_W1 + (size_t)D_FF * D_MODEL)
#define O_WOUT (O_W2 + (size_t)D_FF * D_MODEL)
#define WBUF_TOTAL (O_WOUT + (size_t)D_FF * D_MODEL)
__device__ __align__(1024) __half g_wbuf[WBUF_TOTAL];

// ---------------- helpers ----------------
__device__ __forceinline__ uint32_t smem_u32(const void* p) {
    uint32_t a;
    asm("{ .reg .u64 t; cvta.to.shared.u64 t, %1; cvt.u32.u64 %0, t; }" : "=r"(a) : "l"(p));
    return a;
}
__device__ __forceinline__ void cp_async16(uint32_t dst, const void* src) {
    asm volatile("cp.async.cg.shared.global [%0], [%1], 16;" :: "r"(dst), "l"(src));
}
#define CP_COMMIT() asm volatile("cp.async.commit_group;" ::: "memory")
#define CP_WAIT(N)  asm volatile("cp.async.wait_group %0;" :: "n"(N) : "memory")

__device__ __forceinline__ void mma_f16(float (&d)[4], uint32_t a0, uint32_t a1,
                                        uint32_t a2, uint32_t a3, uint32_t b0, uint32_t b1) {
    asm volatile("mma.sync.aligned.m16n8k16.row.col.f32.f16.f16.f32 "
                 "{%0,%1,%2,%3}, {%4,%5,%6,%7}, {%8,%9}, {%0,%1,%2,%3};"
                 : "+f"(d[0]), "+f"(d[1]), "+f"(d[2]), "+f"(d[3])
                 : "r"(a0), "r"(a1), "r"(a2), "r"(a3), "r"(b0), "r"(b1));
}
#define LDSM4(R0,R1,R2,R3,ADDR) \
    asm volatile("ldmatrix.sync.aligned.m8n8.x4.shared.b16 {%0,%1,%2,%3}, [%4];" \
        : "=r"(R0), "=r"(R1), "=r"(R2), "=r"(R3) : "r"(ADDR))
#define LDSM4T(R0,R1,R2,R3,ADDR) \
    asm volatile("ldmatrix.sync.aligned.m8n8.x4.trans.shared.b16 {%0,%1,%2,%3}, [%4];" \
        : "=r"(R0), "=r"(R1), "=r"(R2), "=r"(R3) : "r"(ADDR))

// ---------------- fp16 tensor-core GEMM: C[M,N] = A[M,K] * B[N,K]^T (+add) -----
#define GS_STRIDE_U32 20
#define GS_STRIDE_B   80
#define STAGE_A_B   10240
#define STAGE_PAIR  20480
#define GSTAGES 3
#define GEMM_SMEM_BYTES (GSTAGES * STAGE_PAIR)

__global__ void __launch_bounds__(256) gemm_f16(const __half* __restrict__ A,
                                                const __half* __restrict__ Bw,
                                                const float* __restrict__ addsrc,
                                                float* __restrict__ C,
                                                __half* __restrict__ Ch,
                                                int Ni, int Ki) {
    extern __shared__ char smem[];
    const uint32_t sbase = smem_u32(smem);
    const int tid = threadIdx.x;
    const int wid = tid >> 5, lane = tid & 31;
    const int g = lane >> 2, t = lane & 3;
    const int wm = wid & 3, wn = wid >> 2;
    const int bm = blockIdx.y * 128, bn = blockIdx.x * 128;

    float acc[2][8][4];
#pragma unroll
    for (int i = 0; i < 2; i++)
#pragma unroll
        for (int j = 0; j < 8; j++)
#pragma unroll
            for (int l = 0; l < 4; l++) acc[i][j][l] = 0.f;

    const int row0 = tid >> 2;
    const int seg0 = tid & 3;
    const __half* aSrc = A  + (size_t)(bm + row0) * Ki + seg0 * 8;
    const __half* bSrc = Bw + (size_t)(bn + row0) * Ki + seg0 * 8;
    const size_t rowJump = (size_t)64 * Ki;
    const uint32_t dOff = (uint32_t)(row0 * GS_STRIDE_B + seg0 * 16);

    const int nk = Ki / 32;

#define LOAD_STAGE(s) do { \
        uint32_t _base = sbase + (uint32_t)((s) % GSTAGES) * STAGE_PAIR + dOff; \
        const __half* _ap = aSrc + (size_t)(s) * 32; \
        const __half* _bp = bSrc + (size_t)(s) * 32; \
        cp_async16(_base, _ap); \
        cp_async16(_base + 64 * GS_STRIDE_B, _ap + rowJump); \
        cp_async16(_base + STAGE_A_B, _bp); \
        cp_async16(_base + STAGE_A_B + 64 * GS_STRIDE_B, _bp + rowJump); \
        CP_COMMIT(); \
    } while (0)

    LOAD_STAGE(0);
    LOAD_STAGE(1);

    for (int kt = 0; kt < nk; kt++) {
        if (kt + 2 < nk) LOAD_STAGE(kt + 2);
        if (kt + 2 < nk)      { CP_WAIT(2); }
        else if (kt + 1 < nk) { CP_WAIT(1); }
        else                  { CP_WAIT(0); }
        __syncthreads();

        const uint32_t* As32 = (const uint32_t*)(smem + (kt % GSTAGES) * STAGE_PAIR);
        const uint32_t* Bs32 = (const uint32_t*)(smem + (kt % GSTAGES) * STAGE_PAIR + STAGE_A_B);

#pragma unroll
        for (int ks = 0; ks < 2; ks++) {
            const int kb = ks * 8;
            uint32_t af[2][4];
#pragma unroll
            for (int mt = 0; mt < 2; mt++) {
                int rb = wm * 32 + mt * 16 + g;
                af[mt][0] = As32[rb * GS_STRIDE_U32 + kb + t];
                af[mt][1] = As32[(rb + 8) * GS_STRIDE_U32 + kb + t];
                af[mt][2] = As32[rb * GS_STRIDE_U32 + kb + t + 4];
                af[mt][3] = As32[(rb + 8) * GS_STRIDE_U32 + kb + t + 4];
            }
#pragma unroll
            for (int nt = 0; nt < 8; nt++) {
                int cb = wn * 64 + nt * 8 + g;
                uint32_t b0 = Bs32[cb * GS_STRIDE_U32 + kb + t];
                uint32_t b1 = Bs32[cb * GS_STRIDE_U32 + kb + t + 4];
                mma_f16(acc[0][nt], af[0][0], af[0][1], af[0][2], af[0][3], b0, b1);
                mma_f16(acc[1][nt], af[1][0], af[1][1], af[1][2], af[1][3], b0, b1);
            }
        }
        __syncthreads();
    }
#undef LOAD_STAGE

#pragma unroll
    for (int mt = 0; mt < 2; mt++) {
#pragma unroll
        for (int nt = 0; nt < 8; nt++) {
            int r = bm + wm * 32 + mt * 16 + g;
            int c = bn + wn * 64 + nt * 8 + t * 2;
            size_t i0 = (size_t)r * Ni + c;
            size_t i1 = i0 + (size_t)8 * Ni;
            if (Ch) {
                __half2 h0 = __floats2half2_rn(acc[mt][nt][0], acc[mt][nt][1]);
                __half2 h1 = __floats2half2_rn(acc[mt][nt][2], acc[mt][nt][3]);
                *(__half2*)(Ch + i0) = h0;
                *(__half2*)(Ch + i1) = h1;
            } else {
                float2 o0 = make_float2(acc[mt][nt][0], acc[mt][nt][1]);
                float2 o1 = make_float2(acc[mt][nt][2], acc[mt][nt][3]);
                if (addsrc) {
                    float2 s0 = *(const float2*)(addsrc + i0);
                    float2 s1 = *(const float2*)(addsrc + i1);
                    o0.x += s0.x; o0.y += s0.y;
                    o1.x += s1.x; o1.y += s1.y;
                }
                *(float2*)(C + i0) = o0;
                *(float2*)(C + i1) = o1;
            }
        }
    }
}

// ---------------- fp32 -> fp16 conversion ----------------
__global__ void __launch_bounds__(256) tohalf_k(const float4* __restrict__ in,
                                                __half2* __restrict__ out, int n4) {
    int i = blockIdx.x * 256 + threadIdx.x;
    if (i < n4) {
        float4 v = in[i];
        out[i * 2]     = __floats2half2_rn(v.x, v.y);
        out[i * 2 + 1] = __floats2half2_rn(v.z, v.w);
    }
}

// ---------------- RMSNorm: one block per row, fp16 out ----------------
__global__ void __launch_bounds__(256) rmsnorm_k(const float* __restrict__ x,
                                                 const float* __restrict__ w,
                                                 __half* __restrict__ out, int Dm) {
    int row = blockIdx.x;
    const float* xr = x + (size_t)row * Dm;
    float ss = 0.f;
    for (int i = threadIdx.x; i < Dm; i += 256) { float v = xr[i]; ss += v * v; }
    __shared__ float red[256];
    red[threadIdx.x] = ss;
    __syncthreads();
    for (int s = 128; s > 0; s >>= 1) {
        if (threadIdx.x < s) red[threadIdx.x] += red[threadIdx.x + s];
        __syncthreads();
    }
    float rms = sqrtf(red[0] / (float)Dm);
    float inv = 1.0f / (rms + 1e-8f);
    __half* orow = out + (size_t)row * Dm;
    for (int i = threadIdx.x; i < Dm; i += 256) orow[i] = __float2half_rn(w[i] * xr[i] * inv);
}

// ---------------- RoPE (in-place on fp16 Q and K) ----------------
__global__ void __launch_bounds__(256) rope_h_k(__half* __restrict__ q, __half* __restrict__ k,
                                                const float* __restrict__ cs,
                                                const float* __restrict__ sn) {
    int idx = blockIdx.x * 256 + threadIdx.x;
    int d = idx & 63;
    int head = (idx >> 6) & (N_HEADS - 1);
    int row = idx >> 10;
    if (row >= M_ROWS) return;
    int t = row & (T_SEQ - 1);
    float c1 = cs[t * HEAD_DIM + d],      s1 = sn[t * HEAD_DIM + d];
    float c2 = cs[t * HEAD_DIM + d + 64], s2 = sn[t * HEAD_DIM + d + 64];
    size_t base = (size_t)row * D_MODEL + head * HEAD_DIM;
    float q1 = __half2float(q[base + d]), q2 = __half2float(q[base + d + 64]);
    q[base + d]      = __float2half_rn(q1 * c1 - q2 * s1);
    q[base + d + 64] = __float2half_rn(q2 * c2 + q1 * s2);
    float k1 = __half2float(k[base + d]), k2 = __half2float(k[base + d + 64]);
    k[base + d]      = __float2half_rn(k1 * c1 - k2 * s1);
    k[base + d + 64] = __float2half_rn(k2 * c2 + k1 * s2);
}

// ---------------- Flash attention via fp16 mma (causal) ----------------
// grid (T/64, H, B), 128 threads = 4 warps; each warp owns 16 Q rows.
// smem: Q + double-buffered K,V tiles (64 x 128 halves, 272B padded rows).
#define FROW_B 272
#define FBUF_B (64 * FROW_B)                 // 17408
#define FLASH_SMEM_BYTES (5 * FBUF_B)        // 87040

__global__ void __launch_bounds__(128) flash_mma_k(const __half* __restrict__ Q,
                                                   const __half* __restrict__ K,
                                                   const __half* __restrict__ V,
                                                   __half* __restrict__ O) {
    extern __shared__ char fsm[];
    const uint32_t sQ  = smem_u32(fsm);
    const uint32_t sK0 = sQ + FBUF_B, sV0 = sQ + 2 * FBUF_B;
    const uint32_t sK1 = sQ + 3 * FBUF_B, sV1 = sQ + 4 * FBUF_B;

    const int qt = blockIdx.x, h = blockIdx.y, b = blockIdx.z;
    const int tid = threadIdx.x;
    const int w = tid >> 5, lane = tid & 31;
    const int g = lane >> 2, t = lane & 3;
    const int r8 = lane & 7, sel = lane >> 3;

    const size_t seq0 = (size_t)b * T_SEQ;
    const size_t col0 = (size_t)h * HEAD_DIM;

    const int lrow = tid >> 4;
    const int lc   = tid & 15;
    const size_t gOff = (size_t)lrow * D_MODEL + lc * 8;
    const uint32_t sOff = (uint32_t)(lrow * FROW_B + lc * 16);

#define FLOAD(SBASE, GPTR) do { \
        const __half* _g = (GPTR) + gOff; \
        uint32_t _s = (SBASE) + sOff; \
        _Pragma("unroll") \
        for (int _i = 0; _i < 8; _i++) { \
            cp_async16(_s, _g); \
            _s += 8 * FROW_B; _g += (size_t)8 * D_MODEL; \
        } \
    } while (0)

    // prologue: Q tile + K/V stage 0
    FLOAD(sQ, Q + (seq0 + (size_t)qt * 64) * D_MODEL + col0);
    FLOAD(sK0, K + seq0 * D_MODEL + col0);
    FLOAD(sV0, V + seq0 * D_MODEL + col0);
    CP_COMMIT();
    CP_WAIT(0);
    __syncthreads();

    // Q fragments: qa[u] covers head-dims 16u..16u+15 for this warp's 16 rows
    uint32_t qa[8][4];
    {
        uint32_t qbase = sQ + (uint32_t)((16 * w + r8 + 8 * (sel & 1)) * FROW_B + (sel >> 1) * 16);
#pragma unroll
        for (int u = 0; u < 8; u++)
            LDSM4(qa[u][0], qa[u][1], qa[u][2], qa[u][3], qbase + u * 32);
    }

    const uint32_t koff = (uint32_t)((r8 + 8 * (sel >> 1)) * FROW_B + (sel & 1) * 16);
    const uint32_t voff = (uint32_t)((8 * (sel & 1) + r8) * FROW_B + (sel >> 1) * 16);

    float oacc[16][4];
#pragma unroll
    for (int j = 0; j < 16; j++) { oacc[j][0] = 0; oacc[j][1] = 0; oacc[j][2] = 0; oacc[j][3] = 0; }
    float mA = -1e30f, mB = -1e30f, lA = 0.f, lB = 0.f;

    const int rowA = qt * 64 + 16 * w + g;   // sequence-local query rows
    const int rowB = rowA + 8;
    const float CEXP = ATTN_SCALE * 1.4426950408889634f;

    for (int kt = 0; kt <= qt; kt++) {
        const uint32_t sK = (kt & 1) ? sK1 : sK0;
        const uint32_t sV = (kt & 1) ? sV1 : sV0;
        const bool more = (kt + 1) <= qt;
        if (more) {
            const uint32_t nK = (kt & 1) ? sK0 : sK1;
            const uint32_t nV = (kt & 1) ? sV0 : sV1;
            FLOAD(nK, K + (seq0 + (size_t)(kt + 1) * 64) * D_MODEL + col0);
            FLOAD(nV, V + (seq0 + (size_t)(kt + 1) * 64) * D_MODEL + col0);
            CP_COMMIT();
        }
        if (kt > 0) {
            if (more) { CP_WAIT(1); } else { CP_WAIT(0); }
            __syncthreads();
        }

        // S = Q K^T (fp32 acc)
        float sacc[8][4];
#pragma unroll
        for (int j = 0; j < 8; j++) { sacc[j][0] = 0; sacc[j][1] = 0; sacc[j][2] = 0; sacc[j][3] = 0; }
#pragma unroll
        for (int u = 0; u < 8; u++) {
#pragma unroll
            for (int jp = 0; jp < 4; jp++) {
                uint32_t k0, k1, k2, k3;
                LDSM4(k0, k1, k2, k3, sK + koff + jp * (16 * FROW_B) + u * 32);
                mma_f16(sacc[2 * jp],     qa[u][0], qa[u][1], qa[u][2], qa[u][3], k0, k1);
                mma_f16(sacc[2 * jp + 1], qa[u][0], qa[u][1], qa[u][2], qa[u][3], k2, k3);
            }
        }

        // causal mask (diagonal tile only)
        if (kt == qt) {
#pragma unroll
            for (int j = 0; j < 8; j++) {
                int c0 = kt * 64 + 8 * j + 2 * t;
                if (c0     > rowA) sacc[j][0] = -1e30f;
                if (c0 + 1 > rowA) sacc[j][1] = -1e30f;
                if (c0     > rowB) sacc[j][2] = -1e30f;
                if (c0 + 1 > rowB) sacc[j][3] = -1e30f;
            }
        }

        // online softmax (registers + quad shuffles)
        float mxA = -1e30f, mxB = -1e30f;
#pragma unroll
        for (int j = 0; j < 8; j++) {
            mxA = fmaxf(mxA, fmaxf(sacc[j][0], sacc[j][1]));
            mxB = fmaxf(mxB, fmaxf(sacc[j][2], sacc[j][3]));
        }
        mxA = fmaxf(mxA, __shfl_xor_sync(0xffffffffu, mxA, 1));
        mxA = fmaxf(mxA, __shfl_xor_sync(0xffffffffu, mxA, 2));
        mxB = fmaxf(mxB, __shfl_xor_sync(0xffffffffu, mxB, 1));
        mxB = fmaxf(mxB, __shfl_xor_sync(0xffffffffu, mxB, 2));
        float mnA = fmaxf(mA, mxA), mnB = fmaxf(mB, mxB);
        float aA = exp2f((mA - mnA) * CEXP), aB = exp2f((mB - mnB) * CEXP);
        mA = mnA; mB = mnB;

        uint32_t ph[8][2];
        float sA = 0.f, sB = 0.f;
#pragma unroll
        for (int j = 0; j < 8; j++) {
            float p0 = exp2f((sacc[j][0] - mnA) * CEXP);
            float p1 = exp2f((sacc[j][1] - mnA) * CEXP);
            float p2 = exp2f((sacc[j][2] - mnB) * CEXP);
            float p3 = exp2f((sacc[j][3] - mnB) * CEXP);
            __half2 h01 = __floats2half2_rn(p0, p1);
            __half2 h23 = __floats2half2_rn(p2, p3);
            ph[j][0] = *(uint32_t*)&h01;
            ph[j][1] = *(uint32_t*)&h23;
            float2 f01 = __half22float2(h01);
            float2 f23 = __half22float2(h23);
            sA += f01.x + f01.y;
            sB += f23.x + f23.y;
        }
        sA += __shfl_xor_sync(0xffffffffu, sA, 1);
        sA += __shfl_xor_sync(0xffffffffu, sA, 2);
        sB += __shfl_xor_sync(0xffffffffu, sB, 1);
        sB += __shfl_xor_sync(0xffffffffu, sB, 2);
        lA = lA * aA + sA;
        lB = lB * aB + sB;

#pragma unroll
        for (int j = 0; j < 16; j++) {
            oacc[j][0] *= aA; oacc[j][1] *= aA;
            oacc[j][2] *= aB; oacc[j][3] *= aB;
        }

        // O += P V  (P repacked from S accumulator registers)
#pragma unroll
        for (int uk = 0; uk < 4; uk++) {
            uint32_t a0 = ph[2 * uk][0], a1 = ph[2 * uk][1];
            uint32_t a2 = ph[2 * uk + 1][0], a3 = ph[2 * uk + 1][1];
#pragma unroll
            for (int jp = 0; jp < 8; jp++) {
                uint32_t v0, v1, v2, v3;
                LDSM4T(v0, v1, v2, v3, sV + voff + uk * (16 * FROW_B) + jp * 32);
                mma_f16(oacc[2 * jp],     a0, a1, a2, a3, v0, v1);
                mma_f16(oacc[2 * jp + 1], a0, a1, a2, a3, v2, v3);
            }
        }
        __syncthreads();
    }
#undef FLOAD

    float iA = 1.f / lA, iB = 1.f / lB;
    __half* orA = O + (seq0 + rowA) * D_MODEL + col0 + 2 * t;
    __half* orB = O + (seq0 + rowB) * D_MODEL + col0 + 2 * t;
#pragma unroll
    for (int j = 0; j < 16; j++) {
        __half2 hA = __floats2half2_rn(oacc[j][0] * iA, oacc[j][1] * iA);
        __half2 hB = __floats2half2_rn(oacc[j][2] * iB, oacc[j][3] * iB);
        *(__half2*)(orA + 8 * j) = hA;
        *(__half2*)(orB + 8 * j) = hB;
    }
}

// ---------------- SiLU gate: f1h = half(silu(f1) * f2) ----------------
__global__ void __launch_bounds__(256) silu_gate_k(const float* __restrict__ f1,
                                                   const float* __restrict__ f2,
                                                   __half* __restrict__ oh, int n) {
    int i = blockIdx.x * 256 + threadIdx.x;
    if (i < n) {
        float z = f1[i];
        float sil = z / (1.0f + expf(-z));
        oh[i] = __float2half_rn(sil * f2[i]);
    }
}

// ---------------- launch ----------------
extern "C" void kernel_launch(void* const* d_in, const int* in_sizes, int n_in,
                              void* d_out, int out_size) {
    const float* x    = (const float*)d_in[0];
    const float* cs   = (const float*)d_in[1];
    const float* sn   = (const float*)d_in[2];
    const float* g1   = (const float*)d_in[4];
    const float* g2   = (const float*)d_in[5];
    const float* Wq   = (const float*)d_in[6];
    const float* Wk   = (const float*)d_in[7];
    const float* Wv   = (const float*)d_in[8];
    const float* Wo   = (const float*)d_in[9];
    const float* W1   = (const float*)d_in[10];
    const float* W2   = (const float*)d_in[11];
    const float* Wout = (const float*)d_in[12];
    float* out = (float*)d_out;

    __half *ph, *pqh, *pkh, *pvh, *pa, *ph2, *pf1h, *pw;
    float *px2, *pf1, *pf2;
    cudaGetSymbolAddress((void**)&ph,   g_h);
    cudaGetSymbolAddress((void**)&pqh,  g_qh);
    cudaGetSymbolAddress((void**)&pkh,  g_kh);
    cudaGetSymbolAddress((void**)&pvh,  g_vh);
    cudaGetSymbolAddress((void**)&pa,   g_a);
    cudaGetSymbolAddress((void**)&px2,  g_x2);
    cudaGetSymbolAddress((void**)&ph2,  g_h2);
    cudaGetSymbolAddress((void**)&pf1,  g_f1);
    cudaGetSymbolAddress((void**)&pf2,  g_f2);
    cudaGetSymbolAddress((void**)&pf1h, g_f1h);
    cudaGetSymbolAddress((void**)&pw,   g_wbuf);

    cudaFuncSetAttribute(gemm_f16, cudaFuncAttributeMaxDynamicSharedMemorySize,
                         GEMM_SMEM_BYTES);
    cudaFuncSetAttribute(flash_mma_k, cudaFuncAttributeMaxDynamicSharedMemorySize,
                         FLASH_SMEM_BYTES);

    // 0) convert weights to fp16
    const int nDD = D_MODEL * D_MODEL;
    const int nFD = D_FF * D_MODEL;
    tohalf_k<<<nDD / 1024, 256>>>((const float4*)Wq,   (__half2*)(pw + O_WQ),   nDD / 4);
    tohalf_k<<<nDD / 1024, 256>>>((const float4*)Wk,   (__half2*)(pw + O_WK),   nDD / 4);
    tohalf_k<<<nDD / 1024, 256>>>((const float4*)Wv,   (__half2*)(pw + O_WV),   nDD / 4);
    tohalf_k<<<nDD / 1024, 256>>>((const float4*)Wo,   (__half2*)(pw + O_WO),   nDD / 4);
    tohalf_k<<<nFD / 1024, 256>>>((const float4*)W1,   (__half2*)(pw + O_W1),   nFD / 4);
    tohalf_k<<<nFD / 1024, 256>>>((const float4*)W2,   (__half2*)(pw + O_W2),   nFD / 4);
    tohalf_k<<<nFD / 1024, 256>>>((const float4*)Wout, (__half2*)(pw + O_WOUT), nFD / 4);

    // 1) h = rmsnorm(x, g1)  (fp16 out)
    rmsnorm_k<<<M_ROWS, 256>>>(x, g1, ph, D_MODEL);

    // 2) Q/K/V projections (fp16 HMMA, half out)
    dim3 gproj(D_MODEL / 128, M_ROWS / 128);
    gemm_f16<<<gproj, 256, GEMM_SMEM_BYTES>>>(ph, pw + O_WQ, nullptr, nullptr, pqh, D_MODEL, D_MODEL);
    gemm_f16<<<gproj, 256, GEMM_SMEM_BYTES>>>(ph, pw + O_WK, nullptr, nullptr, pkh, D_MODEL, D_MODEL);
    gemm_f16<<<gproj, 256, GEMM_SMEM_BYTES>>>(ph, pw + O_WV, nullptr, nullptr, pvh, D_MODEL, D_MODEL);

    // 3) RoPE on Q,K (in-place, fp16)
    rope_h_k<<<(M_ROWS * N_HEADS * 64) / 256, 256>>>(pqh, pkh, cs, sn);

    // 4) causal flash attention (tensor cores) -> fp16
    dim3 gattn(T_SEQ / 64, N_HEADS, B_SZ);
    flash_mma_k<<<gattn, 128, FLASH_SMEM_BYTES>>>(pqh, pkh, pvh, pa);

    // 5) x2 = x + attn @ Wo^T
    gemm_f16<<<gproj, 256, GEMM_SMEM_BYTES>>>(pa, pw + O_WO, x, px2, nullptr, D_MODEL, D_MODEL);

    // 6) h2 = rmsnorm(x2, g2)
    rmsnorm_k<<<M_ROWS, 256>>>(px2, g2, ph2, D_MODEL);

    // 7) FF gates
    dim3 gff(D_FF / 128, M_ROWS / 128);
    gemm_f16<<<gff, 256, GEMM_SMEM_BYTES>>>(ph2, pw + O_W1, nullptr, pf1, nullptr, D_FF, D_MODEL);
    gemm_f16<<<gff, 256, GEMM_SMEM_BYTES>>>(ph2, pw + O_W2, nullptr, pf2, nullptr, D_FF, D_MODEL);

    // 8) f1h = half(silu(f1) * f2)
    int nff = M_ROWS * D_FF;
    silu_gate_k<<<(nff + 255) / 256, 256>>>(pf1, pf2, pf1h, nff);

    // 9) out = x2 + f1h @ Wout^T
    gemm_f16<<<gproj, 256, GEMM_SMEM_BYTES>>>(pf1h, pw + O_WOUT, px2, out, nullptr, D_MODEL, D_FF);
}